// round 2
// baseline (speedup 1.0000x reference)
#include <cuda_runtime.h>
#include <math.h>

#define BB 128
#define TT 12
#define NA 207
#define FF 14
#define HID 128
#define G3 384
#define TOPKN 10
#define HZN 12
#define BN (BB*NA)
#define BTN (BB*TT*NA)

__device__ float g_emb[BN*16];
__device__ float g_L[(size_t)BB*NA*NA];
__device__ float g_tf[(size_t)BN*G3];
__device__ float g_R0[(size_t)BN*G3];
__device__ float g_R1[(size_t)BN*G3];
__device__ float g_R2[(size_t)BN*G3];
__device__ float g_U[(size_t)BN*G3];
__device__ float g_S[(size_t)BN*G3];
__device__ float g_cemb[(size_t)BTN*32];
__device__ float g_z[(size_t)BTN*65];
__device__ float g_gx[(size_t)BTN*G3];
__device__ float g_gh[(size_t)BN*G3];
__device__ float g_dgx[(size_t)BN*G3];
__device__ float g_ctx[(size_t)BN*32];
__device__ float g_h[(size_t)BN*HID];
__device__ float g_cur[BN];
__device__ float g_scal[2];

__device__ __forceinline__ float sigm(float x){ return 1.f/(1.f+expf(-x)); }

__global__ void k_prep(const float* __restrict__ Ap, const float* __restrict__ alpha){
    __shared__ float red[256];
    float m = -1e30f;
    for (int n = threadIdx.x; n < NA; n += 256){
        float s = 0.f;
        for (int j = 0; j < NA; j++) s += Ap[n*NA+j];
        m = fmaxf(m, s);
    }
    red[threadIdx.x] = m; __syncthreads();
    for (int o = 128; o > 0; o >>= 1){
        if (threadIdx.x < o) red[threadIdx.x] = fmaxf(red[threadIdx.x], red[threadIdx.x+o]);
        __syncthreads();
    }
    if (!threadIdx.x){
        float a = sigm(alpha[0]);
        g_scal[0] = a;
        g_scal[1] = fmaxf(1.f, a*red[0] + 1.f - a);
    }
}

__global__ void k_emb(const float* __restrict__ x, const float* __restrict__ w,
                      const float* __restrict__ b){
    int i = blockIdx.x*blockDim.x + threadIdx.x;
    if (i >= BN*16) return;
    int j = i & 15, bn = i >> 4, bb = bn/NA, n = bn%NA;
    float s = x[(((size_t)bb*TT + TT-1)*NA + n)*FF];
    g_emb[i] = tanhf(s*w[j] + b[j]);
}

__global__ void k_adyn(){
    __shared__ float se[NA*16];
    int b = blockIdx.x;
    for (int i = threadIdx.x; i < NA*16; i += blockDim.x) se[i] = g_emb[b*NA*16+i];
    __syncthreads();
    for (int e = threadIdx.x; e < NA*NA; e += blockDim.x){
        int n = e/NA, m = e%NA;
        float s = 0.f;
        #pragma unroll
        for (int j = 0; j < 16; j++) s += se[n*16+j]*se[m*16+j];
        g_L[(size_t)b*NA*NA + e] = fmaxf(s, 0.f);
    }
}

__global__ void k_topk(const float* __restrict__ Ap){
    int warp = (blockIdx.x*blockDim.x + threadIdx.x) >> 5;
    int lane = threadIdx.x & 31;
    if (warp >= BN) return;
    int b = warp/NA, n = warp%NA;
    float* row = g_L + (size_t)b*NA*NA + (size_t)n*NA;
    float v[7], w[7]; int sel = 0;
    #pragma unroll
    for (int s = 0; s < 7; s++){
        int m = s*32 + lane;
        v[s] = (m < NA) ? row[m] : -1e30f;
        w[s] = v[s];
    }
    float topmax = 0.f, sumexp = 0.f;
    for (int it = 0; it < TOPKN; it++){
        float lm = -1e30f; int ls = 0;
        #pragma unroll
        for (int s = 0; s < 7; s++) if (w[s] > lm){ lm = w[s]; ls = s; }
        float gm = lm;
        for (int o = 16; o > 0; o >>= 1) gm = fmaxf(gm, __shfl_xor_sync(~0u, gm, o));
        int my = (lm == gm) ? (ls*32 + lane) : 0x7fffffff;
        int gi = my;
        for (int o = 16; o > 0; o >>= 1) gi = min(gi, __shfl_xor_sync(~0u, gi, o));
        if (!it) topmax = gm;
        sumexp += expf(gm - topmax);
        if ((gi & 31) == lane){ int s = gi >> 5; w[s] = -1e30f; sel |= 1 << s; }
    }
    float e0 = expf(-topmax);
    float inv = 1.f / ((float)(NA-TOPKN)*e0 + sumexp);
    float a = g_scal[0], tol = 2.f/g_scal[1], oma = 1.f - a;
    #pragma unroll
    for (int s = 0; s < 7; s++){
        int m = s*32 + lane;
        if (m < NA){
            float dyn = ((sel >> s) & 1) ? expf(v[s]-topmax)*inv : e0*inv;
            row[m] = tol*(a*Ap[n*NA+m] + oma*dyn) - ((m==n) ? 1.f : 0.f);
        }
    }
}

__global__ void k_tcn(const float* __restrict__ x, const float* __restrict__ w,
                      const float* __restrict__ wb){
    __shared__ float sw[192], sb[64];
    for (int i = threadIdx.x; i < 192; i += blockDim.x) sw[i] = w[i];
    for (int i = threadIdx.x; i < 64; i += blockDim.x) sb[i] = wb[i];
    __syncthreads();
    int bn = blockIdx.x*blockDim.x + threadIdx.x;
    if (bn >= BN) return;
    int b = bn/NA, n = bn%NA;
    float tr[TT+2]; tr[0] = tr[1] = 0.f;
    for (int t = 0; t < TT; t++) tr[t+2] = x[(((size_t)b*TT+t)*NA+n)*FF];
    float* out = g_tf + (size_t)bn*G3;
    for (int t = 0; t < TT; t++){
        #pragma unroll
        for (int f = 0; f < 32; f++){
            float p = sb[f], q = sb[f+32];
            #pragma unroll
            for (int k = 0; k < 3; k++){
                p += tr[t+k]*sw[f*3+k];
                q += tr[t+k]*sw[(f+32)*3+k];
            }
            out[t*32+f] = p*sigm(q);
        }
    }
}

__global__ void k_R(const float* __restrict__ th){
    __shared__ float sth[3072];
    for (int i = threadIdx.x; i < 3072; i += blockDim.x) sth[i] = th[i];
    __syncthreads();
    int r = blockIdx.x*blockDim.x + threadIdx.x;
    if (r >= BTN) return;
    const float* in = g_tf + (size_t)r*32;
    float a[32];
    #pragma unroll
    for (int f = 0; f < 32; f++) a[f] = in[f];
    #pragma unroll
    for (int k = 0; k < 3; k++){
        float acc[32];
        #pragma unroll
        for (int o = 0; o < 32; o++) acc[o] = 0.f;
        #pragma unroll
        for (int f = 0; f < 32; f++){
            float av = a[f];
            #pragma unroll
            for (int o = 0; o < 32; o++) acc[o] += av*sth[k*1024+f*32+o];
        }
        float* op = (k==0 ? g_R0 : (k==1 ? g_R1 : g_R2)) + (size_t)r*32;
        #pragma unroll
        for (int o = 0; o < 32; o++) op[o] = acc[o];
    }
}

__global__ void k_axpy(){
    size_t i = (size_t)blockIdx.x*blockDim.x + threadIdx.x;
    if (i < (size_t)BN*G3) g_R1[i] += 2.f*g_U[i];
}

__global__ void k_cemb(const float* __restrict__ x, const float* __restrict__ cw,
                       const float* __restrict__ cb){
    __shared__ float sw[416], sb2[32];
    for (int i = threadIdx.x; i < 416; i += blockDim.x) sw[i] = cw[i];
    for (int i = threadIdx.x; i < 32; i += blockDim.x) sb2[i] = cb[i];
    __syncthreads();
    int g = blockIdx.x*blockDim.x + threadIdx.x;
    if (g >= BTN) return;
    const float* in = x + (size_t)g*FF + 1;
    float c[13];
    #pragma unroll
    for (int f = 0; f < 13; f++) c[f] = in[f];
    float* op = g_cemb + (size_t)g*32;
    #pragma unroll
    for (int o = 0; o < 32; o++){
        float s = sb2[o];
        #pragma unroll
        for (int f = 0; f < 13; f++) s += c[f]*sw[o*13+f];
        op[o] = fmaxf(s, 0.f);
    }
}

__global__ void k_fusion(const float* __restrict__ x, const float* __restrict__ aw,
                         const float* __restrict__ ab){
    int g = (blockIdx.x*blockDim.x + threadIdx.x) >> 5;
    int lane = threadIdx.x & 31;
    if (g >= BTN) return;
    int b = g/(TT*NA), rem = g - b*TT*NA, t = rem/NA, n = rem - t*NA;
    int bn = b*NA + n;
    const float* sf = g_S + (size_t)bn*G3 + t*32;
    const float* ce = g_cemb + (size_t)g*32;
    float v0 = lane ? sf[lane-1] : x[(size_t)g*FF];
    float v1 = lane ? ce[lane-1] : sf[31];
    float v2 = lane ? 0.f : ce[31];
    float dot = v0*aw[lane] + v1*aw[32+lane] + (lane ? 0.f : v2*aw[64]);
    for (int o = 16; o > 0; o >>= 1) dot += __shfl_xor_sync(~0u, dot, o);
    float attn = sigm(dot + ab[0]);
    float* zr = g_z + (size_t)g*65;
    zr[lane] = v0*attn;
    zr[32+lane] = v1*attn;
    if (!lane) zr[64] = v2*attn;
}

__global__ void k_zeroH(){
    int i = blockIdx.x*blockDim.x + threadIdx.x;
    if (i < BN*HID) g_h[i] = 0.f;
}

__global__ void k_gru_enc(int t2){
    int i = blockIdx.x*blockDim.x + threadIdx.x;
    if (i >= BN*HID) return;
    int r = i >> 7, j = i & 127;
    size_t gxo = ((size_t)(r*TT + t2))*G3, gho = (size_t)r*G3;
    float rg = sigm(g_gx[gxo+j] + g_gh[gho+j]);
    float zg = sigm(g_gx[gxo+128+j] + g_gh[gho+128+j]);
    float ng = tanhf(g_gx[gxo+256+j] + rg*g_gh[gho+256+j]);
    g_h[i] = (1.f-zg)*ng + zg*g_h[i];
}

__global__ void k_gatherctx(const float* __restrict__ x){
    int i = blockIdx.x*blockDim.x + threadIdx.x;
    if (i < BN && !(i & 0)) {}
    if (i >= BN*32) return;
    int r = i >> 5, o = i & 31, b = r/NA, n = r%NA;
    g_ctx[i] = g_cemb[(((size_t)b*TT + TT-1)*NA + n)*32 + o];
    if (!o) g_cur[r] = x[(((size_t)b*TT + TT-1)*NA + n)*FF];
}

__global__ void k_gru_dec(const float* __restrict__ wih, const float* __restrict__ ow,
                          const float* __restrict__ ob, float* __restrict__ out, int step){
    __shared__ float red[4];
    int r = blockIdx.x, j = threadIdx.x;
    float cur = g_cur[r];
    size_t o = (size_t)r*G3;
    float rg = sigm(g_dgx[o+j] + cur*wih[(size_t)j*33] + g_gh[o+j]);
    float zg = sigm(g_dgx[o+128+j] + cur*wih[(size_t)(j+128)*33] + g_gh[o+128+j]);
    float ng = tanhf(g_dgx[o+256+j] + cur*wih[(size_t)(j+256)*33] + rg*g_gh[o+256+j]);
    float h2 = (1.f-zg)*ng + zg*g_h[(size_t)r*HID+j];
    g_h[(size_t)r*HID+j] = h2;
    float p = h2*ow[j];
    for (int of = 16; of > 0; of >>= 1) p += __shfl_xor_sync(~0u, p, of);
    if (!(j & 31)) red[j >> 5] = p;
    __syncthreads();
    if (!j){
        float pr = red[0]+red[1]+red[2]+red[3]+ob[0];
        g_cur[r] = pr;
        out[(size_t)(r/NA)*(HZN*NA) + (size_t)step*NA + (r%NA)] = pr;
    }
}

// C(MxN) = A(MxK) @ B(NxK)^T + bias
template<int BM>
__global__ void gemm_nt(const float* __restrict__ A, int lda,
                        const float* __restrict__ Bm, int ldb,
                        const float* __restrict__ bias,
                        float* __restrict__ C, int ldc, int M, int Nd, int Kd){
    const int TM = BM/16;
    __shared__ float As[16][BM+4];
    __shared__ float Bs[16][68];
    int tid = threadIdx.x, tx = tid & 15, ty = tid >> 4;
    int m0 = blockIdx.y*BM, n0 = blockIdx.x*64;
    float acc[TM][4];
    #pragma unroll
    for (int i = 0; i < TM; i++)
        #pragma unroll
        for (int j = 0; j < 4; j++) acc[i][j] = 0.f;
    const int EA = BM*16/256;
    for (int k0 = 0; k0 < Kd; k0 += 16){
        #pragma unroll
        for (int e = 0; e < EA; e++){
            int idx = tid*EA + e, am = idx >> 4, ak = idx & 15;
            int gm = m0+am, gk = k0+ak;
            As[ak][am] = (gm < M && gk < Kd) ? A[(size_t)gm*lda+gk] : 0.f;
        }
        #pragma unroll
        for (int e = 0; e < 4; e++){
            int idx = tid*4 + e, bn = idx >> 4, bk = idx & 15;
            int gn = n0+bn, gk = k0+bk;
            Bs[bk][bn] = (gn < Nd && gk < Kd) ? Bm[(size_t)gn*ldb+gk] : 0.f;
        }
        __syncthreads();
        #pragma unroll
        for (int kk = 0; kk < 16; kk++){
            float4 b4 = *reinterpret_cast<const float4*>(&Bs[kk][tx*4]);
            float br[4] = {b4.x, b4.y, b4.z, b4.w};
            float ar[TM];
            #pragma unroll
            for (int i4 = 0; i4 < TM/4; i4++){
                float4 a4 = *reinterpret_cast<const float4*>(&As[kk][ty*TM+i4*4]);
                ar[i4*4] = a4.x; ar[i4*4+1] = a4.y; ar[i4*4+2] = a4.z; ar[i4*4+3] = a4.w;
            }
            #pragma unroll
            for (int i = 0; i < TM; i++)
                #pragma unroll
                for (int j = 0; j < 4; j++) acc[i][j] += ar[i]*br[j];
        }
        __syncthreads();
    }
    #pragma unroll
    for (int i = 0; i < TM; i++){
        int gm = m0 + ty*TM + i;
        if (gm >= M) continue;
        #pragma unroll
        for (int j = 0; j < 4; j++){
            int gn = n0 + tx*4 + j;
            if (gn < Nd) C[(size_t)gm*ldc+gn] = acc[i][j] + bias[gn];
        }
    }
}

// batched C = A(MxK)@B(KxN); epi: C = relu(C + E0 - E2)
__global__ void gemm_nn(const float* __restrict__ Ab, int lda, size_t sA,
                        const float* __restrict__ Bb, int ldb, size_t sB,
                        float* __restrict__ Cb, int ldc, size_t sC,
                        const float* __restrict__ E0b, const float* __restrict__ E2b,
                        int epi, int M, int Nd, int Kd){
    const float* A = Ab + (size_t)blockIdx.z*sA;
    const float* Bm = Bb + (size_t)blockIdx.z*sB;
    float* C = Cb + (size_t)blockIdx.z*sC;
    __shared__ float As[16][68], Bs[16][68];
    int tid = threadIdx.x, tx = tid & 15, ty = tid >> 4;
    int m0 = blockIdx.y*64, n0 = blockIdx.x*64;
    float acc[4][4];
    #pragma unroll
    for (int i = 0; i < 4; i++)
        #pragma unroll
        for (int j = 0; j < 4; j++) acc[i][j] = 0.f;
    for (int k0 = 0; k0 < Kd; k0 += 16){
        #pragma unroll
        for (int e = 0; e < 4; e++){
            int idx = tid*4 + e, am = idx >> 4, ak = idx & 15;
            int gm = m0+am, gk = k0+ak;
            As[ak][am] = (gm < M && gk < Kd) ? A[(size_t)gm*lda+gk] : 0.f;
        }
        {
            int bk = tid >> 4, bn4 = (tid & 15)*4;
            #pragma unroll
            for (int e = 0; e < 4; e++){
                int gk = k0+bk, gn = n0+bn4+e;
                Bs[bk][bn4+e] = (gk < Kd && gn < Nd) ? Bm[(size_t)gk*ldb+gn] : 0.f;
            }
        }
        __syncthreads();
        #pragma unroll
        for (int kk = 0; kk < 16; kk++){
            float4 b4 = *reinterpret_cast<const float4*>(&Bs[kk][tx*4]);
            float4 a4 = *reinterpret_cast<const float4*>(&As[kk][ty*4]);
            float ar[4] = {a4.x,a4.y,a4.z,a4.w}, br[4] = {b4.x,b4.y,b4.z,b4.w};
            #pragma unroll
            for (int i = 0; i < 4; i++)
                #pragma unroll
                for (int j = 0; j < 4; j++) acc[i][j] += ar[i]*br[j];
        }
        __syncthreads();
    }
    const float* E0 = E0b ? E0b + (size_t)blockIdx.z*sC : nullptr;
    const float* E2 = E2b ? E2b + (size_t)blockIdx.z*sC : nullptr;
    #pragma unroll
    for (int i = 0; i < 4; i++){
        int gm = m0 + ty*4 + i;
        if (gm >= M) continue;
        #pragma unroll
        for (int j = 0; j < 4; j++){
            int gn = n0 + tx*4 + j;
            if (gn >= Nd) continue;
            size_t off = (size_t)gm*ldc + gn;
            float v = acc[i][j];
            if (epi) v = fmaxf(v + E0[off] - E2[off], 0.f);
            C[off] = v;
        }
    }
}

extern "C" void kernel_launch(void* const* d_in, const int* in_sizes, int n_in,
                              void* d_out, int out_size){
    const float* x = (const float*)d_in[0];
    const float* Ap = (const float*)d_in[1];
    const float* fcw = (const float*)d_in[2];
    const float* fcb = (const float*)d_in[3];
    const float* alpha = (const float*)d_in[4];
    const float* cw = (const float*)d_in[5];
    const float* cb = (const float*)d_in[6];
    const float* tw = (const float*)d_in[7];
    const float* tb = (const float*)d_in[8];
    const float* theta = (const float*)d_in[9];
    const float* aw = (const float*)d_in[10];
    const float* ab = (const float*)d_in[11];
    const float* ewih = (const float*)d_in[12];
    const float* ewhh = (const float*)d_in[13];
    const float* ebih = (const float*)d_in[14];
    const float* ebhh = (const float*)d_in[15];
    const float* dwih = (const float*)d_in[16];
    const float* dwhh = (const float*)d_in[17];
    const float* dbih = (const float*)d_in[18];
    const float* dbhh = (const float*)d_in[19];
    const float* ow = (const float*)d_in[20];
    const float* ob = (const float*)d_in[21];
    float* out = (float*)d_out;
    (void)in_sizes; (void)n_in; (void)out_size;

    float *pL,*pR0,*pR1,*pR2,*pU,*pS,*pZ,*pGX,*pGH,*pH,*pCtx,*pDgx;
    cudaGetSymbolAddress((void**)&pL, g_L);
    cudaGetSymbolAddress((void**)&pR0, g_R0);
    cudaGetSymbolAddress((void**)&pR1, g_R1);
    cudaGetSymbolAddress((void**)&pR2, g_R2);
    cudaGetSymbolAddress((void**)&pU, g_U);
    cudaGetSymbolAddress((void**)&pS, g_S);
    cudaGetSymbolAddress((void**)&pZ, g_z);
    cudaGetSymbolAddress((void**)&pGX, g_gx);
    cudaGetSymbolAddress((void**)&pGH, g_gh);
    cudaGetSymbolAddress((void**)&pH, g_h);
    cudaGetSymbolAddress((void**)&pCtx, g_ctx);
    cudaGetSymbolAddress((void**)&pDgx, g_dgx);

    k_prep<<<1,256>>>(Ap, alpha);
    k_emb<<<(BN*16+255)/256,256>>>(x, fcw, fcb);
    k_adyn<<<BB,256>>>();
    k_topk<<<(BN+7)/8,256>>>(Ap);

    k_tcn<<<(BN+255)/256,256>>>(x, tw, tb);
    k_R<<<(BTN+255)/256,256>>>(theta);
    {
        dim3 g(G3/64, (NA+63)/64, BB);
        gemm_nn<<<g,256>>>(pL, NA, (size_t)NA*NA, pR2, G3, (size_t)NA*G3,
                           pU, G3, (size_t)NA*G3, nullptr, nullptr, 0, NA, G3, NA);
        k_axpy<<<(int)(((size_t)BN*G3+255)/256),256>>>();
        gemm_nn<<<g,256>>>(pL, NA, (size_t)NA*NA, pR1, G3, (size_t)NA*G3,
                           pS, G3, (size_t)NA*G3, pR0, pR2, 1, NA, G3, NA);
    }

    k_cemb<<<(BTN+255)/256,256>>>(x, cw, cb);
    k_fusion<<<(BTN*32+255)/256,256>>>(x, aw, ab);

    gemm_nt<128><<<dim3(G3/64, BTN/128),256>>>(pZ, 65, ewih, 65, ebih, pGX, G3, BTN, G3, 65);
    k_zeroH<<<(BN*HID+255)/256,256>>>();
    for (int t = 0; t < TT; t++){
        gemm_nt<128><<<dim3(G3/64, BN/128),256>>>(pH, HID, ewhh, HID, ebhh, pGH, G3, BN, G3, HID);
        k_gru_enc<<<(BN*HID+255)/256,256>>>(t);
    }

    k_gatherctx<<<(BN*32+255)/256,256>>>(x);
    gemm_nt<64><<<dim3(G3/64, (BN+63)/64),256>>>(pCtx, 32, dwih+1, 33, dbih, pDgx, G3, BN, G3, 32);
    for (int s = 0; s < HZN; s++){
        gemm_nt<128><<<dim3(G3/64, BN/128),256>>>(pH, HID, dwhh, HID, dbhh, pGH, G3, BN, G3, HID);
        k_gru_dec<<<BN,128>>>(dwih, ow, ob, out, s);
    }
}

// round 3
// speedup vs baseline: 1.6700x; 1.6700x over previous
#include <cuda_runtime.h>
#include <stdint.h>
#include <math.h>

#define BB 128
#define TT 12
#define NA 207
#define FF 14
#define HID 128
#define G3 384
#define TOPKN 10
#define HZN 12
#define BN (BB*NA)
#define BTN (BB*TT*NA)
#define ZP 96

__device__ float g_emb[BN*16];
__device__ float g_L[(size_t)BB*NA*NA];
__device__ float g_tf[(size_t)BN*G3];
__device__ float g_R0[(size_t)BN*G3];
__device__ float g_R1[(size_t)BN*G3];
__device__ float g_R2[(size_t)BN*G3];
__device__ float g_U[(size_t)BN*G3];
__device__ float g_S[(size_t)BN*G3];
__device__ float g_cemb[(size_t)BTN*32];
__device__ float g_z[(size_t)BTN*ZP];
__device__ float g_gx[(size_t)BTN*G3];
__device__ float g_dgx[(size_t)BN*G3];
__device__ float g_ctx[(size_t)BN*32];
__device__ float g_h[(size_t)BN*HID];
__device__ float g_cur[BN];
__device__ float g_scal[2];
__device__ float g_wihp[G3*ZP];
__device__ float g_dwihp[G3*32];

__device__ __forceinline__ float sigm(float x){ return 1.f/(1.f+expf(-x)); }

__device__ __forceinline__ void cpa(uint32_t dst, const float* src){
    asm volatile("cp.async.cg.shared.global [%0], [%1], 16;" :: "r"(dst), "l"(src));
}
__device__ __forceinline__ void mma_tf32(float* c, const uint32_t* a, uint32_t b0, uint32_t b1){
    asm volatile("mma.sync.aligned.m16n8k8.row.col.f32.tf32.tf32.f32 "
        "{%0,%1,%2,%3}, {%4,%5,%6,%7}, {%8,%9}, {%0,%1,%2,%3};"
        : "+f"(c[0]),"+f"(c[1]),"+f"(c[2]),"+f"(c[3])
        : "r"(a[0]),"r"(a[1]),"r"(a[2]),"r"(a[3]), "r"(b0),"r"(b1));
}

#define ASZ (64*36)
#define BSZ (384*36)
#define SMEMB ((2*(ASZ+BSZ))*4)

// C(M x 384) = A(M x K) @ Bw(384 x K)^T [+ GRU epilogue]
// EPI=0: C = acc + bias.  EPI=1: encoder GRU step t.  EPI=2: decoder GRU.
// Requires M%64==0, K%32==0, lda%4==0, ldb%4==0.
template<int EPI>
__global__ void __launch_bounds__(256) gemm_gru(
    const float* __restrict__ A, int lda, int K,
    const float* __restrict__ Bw, int ldb,
    const float* __restrict__ bias,
    float* __restrict__ C,
    const float* __restrict__ gx,
    const float* __restrict__ wcol,
    int t)
{
    extern __shared__ float sm[];
    const int tid = threadIdx.x, lane = tid & 31, wid = tid >> 5;
    const int wm = wid & 1, wn = wid >> 1;
    const int m0 = blockIdx.x*64;
    uint32_t sb = (uint32_t)__cvta_generic_to_shared(sm);
    float acc[24][4];
    #pragma unroll
    for (int i = 0; i < 24; i++){
        acc[i][0]=0.f; acc[i][1]=0.f; acc[i][2]=0.f; acc[i][3]=0.f;
    }
    const int nc = K >> 5;

    // preload chunk 0
    {
        const int c = 0, s = 0;
        #pragma unroll
        for (int i = 0; i < 2; i++){
            int idx = tid + i*256, row = idx >> 3, c4 = idx & 7;
            cpa(sb + (uint32_t)((s*ASZ + row*36 + c4*4)*4),
                A + (size_t)(m0+row)*lda + c*32 + c4*4);
        }
        #pragma unroll
        for (int i = 0; i < 12; i++){
            int idx = tid + i*256, row = idx >> 3, c4 = idx & 7;
            cpa(sb + (uint32_t)((2*ASZ + s*BSZ + row*36 + c4*4)*4),
                Bw + (size_t)row*ldb + c*32 + c4*4);
        }
        asm volatile("cp.async.commit_group;");
    }

    for (int c = 0; c < nc; c++){
        if (c+1 < nc){
            int s = (c+1) & 1;
            #pragma unroll
            for (int i = 0; i < 2; i++){
                int idx = tid + i*256, row = idx >> 3, c4 = idx & 7;
                cpa(sb + (uint32_t)((s*ASZ + row*36 + c4*4)*4),
                    A + (size_t)(m0+row)*lda + (c+1)*32 + c4*4);
            }
            #pragma unroll
            for (int i = 0; i < 12; i++){
                int idx = tid + i*256, row = idx >> 3, c4 = idx & 7;
                cpa(sb + (uint32_t)((2*ASZ + s*BSZ + row*36 + c4*4)*4),
                    Bw + (size_t)row*ldb + (c+1)*32 + c4*4);
            }
            asm volatile("cp.async.commit_group;");
            asm volatile("cp.async.wait_group 1;");
        } else {
            asm volatile("cp.async.wait_group 0;");
        }
        __syncthreads();
        const float* As_ = sm + (c&1)*ASZ;
        const float* Bs_ = sm + 2*ASZ + (c&1)*BSZ;
        #pragma unroll
        for (int k8 = 0; k8 < 4; k8++){
            int kc = k8*8 + (lane & 3);
            uint32_t a[2][4];
            #pragma unroll
            for (int mf = 0; mf < 2; mf++){
                int r = wm*32 + mf*16 + (lane >> 2);
                a[mf][0] = __float_as_uint(As_[r*36 + kc]);
                a[mf][1] = __float_as_uint(As_[(r+8)*36 + kc]);
                a[mf][2] = __float_as_uint(As_[r*36 + kc + 4]);
                a[mf][3] = __float_as_uint(As_[(r+8)*36 + kc + 4]);
            }
            #pragma unroll
            for (int g = 0; g < 3; g++)
            #pragma unroll
            for (int nf = 0; nf < 4; nf++){
                int br = g*128 + wn*32 + nf*8 + (lane >> 2);
                uint32_t b0 = __float_as_uint(Bs_[br*36 + kc]);
                uint32_t b1 = __float_as_uint(Bs_[br*36 + kc + 4]);
                mma_tf32(acc[(g*2+0)*4+nf], a[0], b0, b1);
                mma_tf32(acc[(g*2+1)*4+nf], a[1], b0, b1);
            }
        }
        __syncthreads();
    }

    #pragma unroll
    for (int mf = 0; mf < 2; mf++)
    #pragma unroll
    for (int nf = 0; nf < 4; nf++)
    #pragma unroll
    for (int e = 0; e < 4; e++){
        int grow = m0 + wm*32 + mf*16 + (lane >> 2) + ((e & 2) ? 8 : 0);
        int j = wn*32 + nf*8 + (lane & 3)*2 + (e & 1);
        float vr = acc[(0*2+mf)*4+nf][e] + bias[j];
        float vz = acc[(1*2+mf)*4+nf][e] + bias[128+j];
        float vn = acc[(2*2+mf)*4+nf][e] + bias[256+j];
        if (EPI == 0){
            C[(size_t)grow*G3 + j] = vr;
            C[(size_t)grow*G3 + 128 + j] = vz;
            C[(size_t)grow*G3 + 256 + j] = vn;
        } else {
            float gr, gz, gn;
            if (EPI == 1){
                size_t gxr = ((size_t)grow*TT + t)*G3;
                gr = gx[gxr + j]; gz = gx[gxr + 128 + j]; gn = gx[gxr + 256 + j];
            } else {
                float cur = g_cur[grow];
                size_t gxr = (size_t)grow*G3;
                gr = gx[gxr + j]       + cur*wcol[(size_t)j*33];
                gz = gx[gxr + 128 + j] + cur*wcol[(size_t)(128+j)*33];
                gn = gx[gxr + 256 + j] + cur*wcol[(size_t)(256+j)*33];
            }
            float rg = sigm(gr + vr);
            float zg = sigm(gz + vz);
            float ng = tanhf(gn + rg*vn);
            size_t hi = (size_t)grow*HID + j;
            g_h[hi] = (1.f - zg)*ng + zg*g_h[hi];
        }
    }
}

// ------------------------------ small kernels -------------------------------
__global__ void k_prep(const float* __restrict__ Ap, const float* __restrict__ alpha){
    __shared__ float red[256];
    float m = -1e30f;
    for (int n = threadIdx.x; n < NA; n += 256){
        float s = 0.f;
        for (int j = 0; j < NA; j++) s += Ap[n*NA+j];
        m = fmaxf(m, s);
    }
    red[threadIdx.x] = m; __syncthreads();
    for (int o = 128; o > 0; o >>= 1){
        if (threadIdx.x < o) red[threadIdx.x] = fmaxf(red[threadIdx.x], red[threadIdx.x+o]);
        __syncthreads();
    }
    if (!threadIdx.x){
        float a = sigm(alpha[0]);
        g_scal[0] = a;
        g_scal[1] = fmaxf(1.f, a*red[0] + 1.f - a);
    }
}

__global__ void k_padw(const float* __restrict__ ewih, const float* __restrict__ dwih){
    int i = blockIdx.x*blockDim.x + threadIdx.x;
    if (i < G3*ZP){
        int n = i/ZP, k = i%ZP;
        g_wihp[i] = (k < 65) ? ewih[n*65+k] : 0.f;
    }
    int i2 = i - G3*ZP;
    if (i2 >= 0 && i2 < G3*32){
        int n = i2/32, k = i2%32;
        g_dwihp[i2] = dwih[n*33 + 1 + k];
    }
}

__global__ void k_emb(const float* __restrict__ x, const float* __restrict__ w,
                      const float* __restrict__ b){
    int i = blockIdx.x*blockDim.x + threadIdx.x;
    if (i >= BN*16) return;
    int j = i & 15, bn = i >> 4, bb = bn/NA, n = bn%NA;
    float s = x[(((size_t)bb*TT + TT-1)*NA + n)*FF];
    g_emb[i] = tanhf(s*w[j] + b[j]);
}

__global__ void k_adyn(){
    __shared__ float se[NA*16];
    int b = blockIdx.x;
    for (int i = threadIdx.x; i < NA*16; i += blockDim.x) se[i] = g_emb[b*NA*16+i];
    __syncthreads();
    for (int e = threadIdx.x; e < NA*NA; e += blockDim.x){
        int n = e/NA, m = e%NA;
        float s = 0.f;
        #pragma unroll
        for (int j = 0; j < 16; j++) s += se[n*16+j]*se[m*16+j];
        g_L[(size_t)b*NA*NA + e] = fmaxf(s, 0.f);
    }
}

__global__ void k_topk(const float* __restrict__ Ap){
    int warp = (blockIdx.x*blockDim.x + threadIdx.x) >> 5;
    int lane = threadIdx.x & 31;
    if (warp >= BN) return;
    int b = warp/NA, n = warp%NA;
    float* row = g_L + (size_t)b*NA*NA + (size_t)n*NA;
    float v[7], w[7]; int sel = 0;
    #pragma unroll
    for (int s = 0; s < 7; s++){
        int m = s*32 + lane;
        v[s] = (m < NA) ? row[m] : -1e30f;
        w[s] = v[s];
    }
    float topmax = 0.f, sumexp = 0.f;
    for (int it = 0; it < TOPKN; it++){
        float lm = -1e30f; int ls = 0;
        #pragma unroll
        for (int s = 0; s < 7; s++) if (w[s] > lm){ lm = w[s]; ls = s; }
        float gm = lm;
        for (int o = 16; o > 0; o >>= 1) gm = fmaxf(gm, __shfl_xor_sync(~0u, gm, o));
        int my = (lm == gm) ? (ls*32 + lane) : 0x7fffffff;
        int gi = my;
        for (int o = 16; o > 0; o >>= 1) gi = min(gi, __shfl_xor_sync(~0u, gi, o));
        if (!it) topmax = gm;
        sumexp += expf(gm - topmax);
        if ((gi & 31) == lane){ int s = gi >> 5; w[s] = -1e30f; sel |= 1 << s; }
    }
    float e0 = expf(-topmax);
    float inv = 1.f / ((float)(NA-TOPKN)*e0 + sumexp);
    float a = g_scal[0], tol = 2.f/g_scal[1], oma = 1.f - a;
    #pragma unroll
    for (int s = 0; s < 7; s++){
        int m = s*32 + lane;
        if (m < NA){
            float dyn = ((sel >> s) & 1) ? expf(v[s]-topmax)*inv : e0*inv;
            row[m] = tol*(a*Ap[n*NA+m] + oma*dyn) - ((m==n) ? 1.f : 0.f);
        }
    }
}

__global__ void k_tcn(const float* __restrict__ x, const float* __restrict__ w,
                      const float* __restrict__ wb){
    __shared__ float sw[192], sb2[64];
    for (int i = threadIdx.x; i < 192; i += blockDim.x) sw[i] = w[i];
    for (int i = threadIdx.x; i < 64; i += blockDim.x) sb2[i] = wb[i];
    __syncthreads();
    int bn = blockIdx.x*blockDim.x + threadIdx.x;
    if (bn >= BN) return;
    int b = bn/NA, n = bn%NA;
    float tr[TT+2]; tr[0] = tr[1] = 0.f;
    for (int t = 0; t < TT; t++) tr[t+2] = x[(((size_t)b*TT+t)*NA+n)*FF];
    float* out = g_tf + (size_t)bn*G3;
    for (int t = 0; t < TT; t++){
        #pragma unroll
        for (int f = 0; f < 32; f++){
            float p = sb2[f], q = sb2[f+32];
            #pragma unroll
            for (int k = 0; k < 3; k++){
                p += tr[t+k]*sw[f*3+k];
                q += tr[t+k]*sw[(f+32)*3+k];
            }
            out[t*32+f] = p*sigm(q);
        }
    }
}

__global__ void k_R(const float* __restrict__ th){
    __shared__ float sth[3072];
    for (int i = threadIdx.x; i < 3072; i += blockDim.x) sth[i] = th[i];
    __syncthreads();
    int r = blockIdx.x*blockDim.x + threadIdx.x;
    if (r >= BTN) return;
    const float* in = g_tf + (size_t)r*32;
    float a[32];
    #pragma unroll
    for (int f = 0; f < 32; f++) a[f] = in[f];
    #pragma unroll
    for (int k = 0; k < 3; k++){
        float acc2[32];
        #pragma unroll
        for (int o = 0; o < 32; o++) acc2[o] = 0.f;
        #pragma unroll
        for (int f = 0; f < 32; f++){
            float av = a[f];
            #pragma unroll
            for (int o = 0; o < 32; o++) acc2[o] += av*sth[k*1024+f*32+o];
        }
        float* op = (k==0 ? g_R0 : (k==1 ? g_R1 : g_R2)) + (size_t)r*32;
        #pragma unroll
        for (int o = 0; o < 32; o++) op[o] = acc2[o];
    }
}

__global__ void k_axpy(){
    size_t i = (size_t)blockIdx.x*blockDim.x + threadIdx.x;
    if (i < (size_t)BN*G3) g_R1[i] += 2.f*g_U[i];
}

__global__ void k_cemb(const float* __restrict__ x, const float* __restrict__ cw,
                       const float* __restrict__ cb){
    __shared__ float sw[416], sb2[32];
    for (int i = threadIdx.x; i < 416; i += blockDim.x) sw[i] = cw[i];
    for (int i = threadIdx.x; i < 32; i += blockDim.x) sb2[i] = cb[i];
    __syncthreads();
    int g = blockIdx.x*blockDim.x + threadIdx.x;
    if (g >= BTN) return;
    const float* in = x + (size_t)g*FF + 1;
    float c[13];
    #pragma unroll
    for (int f = 0; f < 13; f++) c[f] = in[f];
    float* op = g_cemb + (size_t)g*32;
    #pragma unroll
    for (int o = 0; o < 32; o++){
        float s = sb2[o];
        #pragma unroll
        for (int f = 0; f < 13; f++) s += c[f]*sw[o*13+f];
        op[o] = fmaxf(s, 0.f);
    }
}

__global__ void k_fusion(const float* __restrict__ x, const float* __restrict__ aw,
                         const float* __restrict__ ab){
    int g = (blockIdx.x*blockDim.x + threadIdx.x) >> 5;
    int lane = threadIdx.x & 31;
    if (g >= BTN) return;
    int b = g/(TT*NA), rem = g - b*TT*NA, t = rem/NA, n = rem - t*NA;
    int bn = b*NA + n;
    const float* sf = g_S + (size_t)bn*G3 + t*32;
    const float* ce = g_cemb + (size_t)g*32;
    float v0 = lane ? sf[lane-1] : x[(size_t)g*FF];
    float v1 = lane ? ce[lane-1] : sf[31];
    float v2 = lane ? 0.f : ce[31];
    float dot = v0*aw[lane] + v1*aw[32+lane] + (lane ? 0.f : v2*aw[64]);
    for (int o = 16; o > 0; o >>= 1) dot += __shfl_xor_sync(~0u, dot, o);
    float attn = sigm(dot + ab[0]);
    float* zr = g_z + (size_t)g*ZP;
    zr[lane] = v0*attn;
    zr[32+lane] = v1*attn;
    if (!lane) zr[64] = v2*attn;
    else zr[64+lane] = 0.f;   // pad cols 65..95
}

__global__ void k_zeroH(){
    int i = blockIdx.x*blockDim.x + threadIdx.x;
    if (i < BN*HID) g_h[i] = 0.f;
}

__global__ void k_gatherctx(const float* __restrict__ x){
    int i = blockIdx.x*blockDim.x + threadIdx.x;
    if (i >= BN*32) return;
    int r = i >> 5, o = i & 31, b = r/NA, n = r%NA;
    g_ctx[i] = g_cemb[(((size_t)b*TT + TT-1)*NA + n)*32 + o];
    if (!o) g_cur[r] = x[(((size_t)b*TT + TT-1)*NA + n)*FF];
}

__global__ void k_pred(const float* __restrict__ ow, const float* __restrict__ ob,
                       float* __restrict__ out, int step){
    int warp = (blockIdx.x*blockDim.x + threadIdx.x) >> 5;
    int lane = threadIdx.x & 31;
    if (warp >= BN) return;
    const float* h = g_h + (size_t)warp*HID;
    float p = 0.f;
    #pragma unroll
    for (int i = 0; i < 4; i++) p += h[lane + i*32]*ow[lane + i*32];
    for (int o = 16; o > 0; o >>= 1) p += __shfl_xor_sync(~0u, p, o);
    if (!lane){
        float pr = p + ob[0];
        g_cur[warp] = pr;
        out[(size_t)(warp/NA)*(HZN*NA) + (size_t)step*NA + (warp%NA)] = pr;
    }
}

// batched C = A(MxK)@B(KxN); epi: C = relu(C + E0 - E2)  (fp32, Chebyshev)
__global__ void gemm_nn(const float* __restrict__ Ab, int lda, size_t sA,
                        const float* __restrict__ Bb, int ldb, size_t sB,
                        float* __restrict__ Cb, int ldc, size_t sC,
                        const float* __restrict__ E0b, const float* __restrict__ E2b,
                        int epi, int M, int Nd, int Kd){
    const float* A = Ab + (size_t)blockIdx.z*sA;
    const float* Bm = Bb + (size_t)blockIdx.z*sB;
    float* C = Cb + (size_t)blockIdx.z*sC;
    __shared__ float As[16][68], Bs[16][68];
    int tid = threadIdx.x, tx = tid & 15, ty = tid >> 4;
    int m0 = blockIdx.y*64, n0 = blockIdx.x*64;
    float acc[4][4];
    #pragma unroll
    for (int i = 0; i < 4; i++)
        #pragma unroll
        for (int j = 0; j < 4; j++) acc[i][j] = 0.f;
    for (int k0 = 0; k0 < Kd; k0 += 16){
        #pragma unroll
        for (int e = 0; e < 4; e++){
            int idx = tid*4 + e, am = idx >> 4, ak = idx & 15;
            int gm = m0+am, gk = k0+ak;
            As[ak][am] = (gm < M && gk < Kd) ? A[(size_t)gm*lda+gk] : 0.f;
        }
        {
            int bk = tid >> 4, bn4 = (tid & 15)*4;
            #pragma unroll
            for (int e = 0; e < 4; e++){
                int gk = k0+bk, gn = n0+bn4+e;
                Bs[bk][bn4+e] = (gk < Kd && gn < Nd) ? Bm[(size_t)gk*ldb+gn] : 0.f;
            }
        }
        __syncthreads();
        #pragma unroll
        for (int kk = 0; kk < 16; kk++){
            float4 b4 = *reinterpret_cast<const float4*>(&Bs[kk][tx*4]);
            float4 a4 = *reinterpret_cast<const float4*>(&As[kk][ty*4]);
            float ar[4] = {a4.x,a4.y,a4.z,a4.w}, br[4] = {b4.x,b4.y,b4.z,b4.w};
            #pragma unroll
            for (int i = 0; i < 4; i++)
                #pragma unroll
                for (int j = 0; j < 4; j++) acc[i][j] += ar[i]*br[j];
        }
        __syncthreads();
    }
    const float* E0 = E0b ? E0b + (size_t)blockIdx.z*sC : nullptr;
    const float* E2 = E2b ? E2b + (size_t)blockIdx.z*sC : nullptr;
    #pragma unroll
    for (int i = 0; i < 4; i++){
        int gm = m0 + ty*4 + i;
        if (gm >= M) continue;
        #pragma unroll
        for (int j = 0; j < 4; j++){
            int gn = n0 + tx*4 + j;
            if (gn >= Nd) continue;
            size_t off = (size_t)gm*ldc + gn;
            float v = acc[i][j];
            if (epi) v = fmaxf(v + E0[off] - E2[off], 0.f);
            C[off] = v;
        }
    }
}

extern "C" void kernel_launch(void* const* d_in, const int* in_sizes, int n_in,
                              void* d_out, int out_size){
    const float* x = (const float*)d_in[0];
    const float* Ap = (const float*)d_in[1];
    const float* fcw = (const float*)d_in[2];
    const float* fcb = (const float*)d_in[3];
    const float* alpha = (const float*)d_in[4];
    const float* cw = (const float*)d_in[5];
    const float* cb = (const float*)d_in[6];
    const float* tw = (const float*)d_in[7];
    const float* tb = (const float*)d_in[8];
    const float* theta = (const float*)d_in[9];
    const float* aw = (const float*)d_in[10];
    const float* ab = (const float*)d_in[11];
    const float* ewih = (const float*)d_in[12];
    const float* ewhh = (const float*)d_in[13];
    const float* ebih = (const float*)d_in[14];
    const float* ebhh = (const float*)d_in[15];
    const float* dwih = (const float*)d_in[16];
    const float* dwhh = (const float*)d_in[17];
    const float* dbih = (const float*)d_in[18];
    const float* dbhh = (const float*)d_in[19];
    const float* ow = (const float*)d_in[20];
    const float* ob = (const float*)d_in[21];
    float* out = (float*)d_out;
    (void)in_sizes; (void)n_in; (void)out_size;

    static int inited = 0;
    if (!inited){
        cudaFuncSetAttribute(gemm_gru<0>, cudaFuncAttributeMaxDynamicSharedMemorySize, SMEMB);
        cudaFuncSetAttribute(gemm_gru<1>, cudaFuncAttributeMaxDynamicSharedMemorySize, SMEMB);
        cudaFuncSetAttribute(gemm_gru<2>, cudaFuncAttributeMaxDynamicSharedMemorySize, SMEMB);
        inited = 1;
    }

    float *pL,*pR0,*pR1,*pR2,*pU,*pS,*pZ,*pGX,*pH,*pCtx,*pDgx,*pWih,*pDwih;
    cudaGetSymbolAddress((void**)&pL, g_L);
    cudaGetSymbolAddress((void**)&pR0, g_R0);
    cudaGetSymbolAddress((void**)&pR1, g_R1);
    cudaGetSymbolAddress((void**)&pR2, g_R2);
    cudaGetSymbolAddress((void**)&pU, g_U);
    cudaGetSymbolAddress((void**)&pS, g_S);
    cudaGetSymbolAddress((void**)&pZ, g_z);
    cudaGetSymbolAddress((void**)&pGX, g_gx);
    cudaGetSymbolAddress((void**)&pH, g_h);
    cudaGetSymbolAddress((void**)&pCtx, g_ctx);
    cudaGetSymbolAddress((void**)&pDgx, g_dgx);
    cudaGetSymbolAddress((void**)&pWih, g_wihp);
    cudaGetSymbolAddress((void**)&pDwih, g_dwihp);

    k_prep<<<1,256>>>(Ap, alpha);
    k_padw<<<(G3*ZP + G3*32 + 255)/256,256>>>(ewih, dwih);
    k_emb<<<(BN*16+255)/256,256>>>(x, fcw, fcb);
    k_adyn<<<BB,256>>>();
    k_topk<<<(BN+7)/8,256>>>(Ap);

    k_tcn<<<(BN+255)/256,256>>>(x, tw, tb);
    k_R<<<(BTN+255)/256,256>>>(theta);
    {
        dim3 g(G3/64, (NA+63)/64, BB);
        gemm_nn<<<g,256>>>(pL, NA, (size_t)NA*NA, pR2, G3, (size_t)NA*G3,
                           pU, G3, (size_t)NA*G3, nullptr, nullptr, 0, NA, G3, NA);
        k_axpy<<<(int)(((size_t)BN*G3+255)/256),256>>>();
        gemm_nn<<<g,256>>>(pL, NA, (size_t)NA*NA, pR1, G3, (size_t)NA*G3,
                           pS, G3, (size_t)NA*G3, pR0, pR2, 1, NA, G3, NA);
    }

    k_cemb<<<(BTN+255)/256,256>>>(x, cw, cb);
    k_fusion<<<(BTN*32+255)/256,256>>>(x, aw, ab);

    // encoder input gates: gx = z @ wih_pad^T + bih   (M=BTN, K=96)
    gemm_gru<0><<<BTN/64,256,SMEMB>>>(pZ, ZP, ZP, pWih, ZP, ebih, pGX, nullptr, nullptr, 0);
    k_zeroH<<<(BN*HID+255)/256,256>>>();
    for (int t = 0; t < TT; t++)
        gemm_gru<1><<<BN/64,256,SMEMB>>>(pH, HID, HID, ewhh, HID, ebhh, nullptr, pGX, nullptr, t);

    k_gatherctx<<<(BN*32+255)/256,256>>>(x);
    gemm_gru<0><<<BN/64,256,SMEMB>>>(pCtx, 32, 32, pDwih, 32, dbih, pDgx, nullptr, nullptr, 0);
    for (int s = 0; s < HZN; s++){
        gemm_gru<2><<<BN/64,256,SMEMB>>>(pH, HID, HID, dwhh, HID, dbhh, nullptr, pDgx, dwih, 0);
        k_pred<<<(BN*32+255)/256,256>>>(ow, ob, out, s);
    }
}